// round 11
// baseline (speedup 1.0000x reference)
#include <cuda_runtime.h>

// DerivativeNet forward, direction='x'  — FINAL (practical HBM roofline)
// u:    [B=16, C=2, H=1024, W=1024] float32
// mask: [B=16, 1,   H=1024, W=1024] float32 (0.0 / 1.0)
// out = eroded*central + edge1*forward + edge2*backward (zero-padded, h=0.01)
//
// edge1 = (cumsum==1)        == [first_set, second_set)
// edge2 = (cumsum==max)&mask == {last_set}
// Per element: out = wp*u[i+1] + w0*u[i] + wm*u[i-1], weights shared by channels.
// Champion structure: 1 CTA per row, 256 thr x 4 elems, register-resident
// stencil, warp-shuffle halos, O(1) ballot merge, evict-first stores,
// LOP3-window erosion, evict-first mask read.

#define HEIGHT  1024
#define INV_H   100.0f
#define INV_2H  50.0f
#define NT      256
#define BIG     0x7fffffff

__global__ __launch_bounds__(NT, 6)
void dnet_kernel(const float* __restrict__ u,
                 const float* __restrict__ mask,
                 float* __restrict__ out)
{
    const int tid  = threadIdx.x;
    const int lane = tid & 31;
    const int wid  = tid >> 5;               // 0..7

    __shared__ int   wfs[8], wss[8], wls[8];             // per-warp first/second/last
    __shared__ int   em_last[8], em_first[8];            // warp-edge mask bits
    __shared__ float ea_last[8], ea_first[8];            // warp-edge u ch0
    __shared__ float ec_last[8], ec_first[8];            // warp-edge u ch1

    const unsigned row   = blockIdx.x;                   // b*HEIGHT + y
    const unsigned b     = row >> 10;
    const unsigned y     = row & (HEIGHT - 1);
    const unsigned base0 = ((b * 2u) << 20) | (y << 10); // u channel 0, elements
    const unsigned base1 = base0 + (1u << 20);           // u channel 1

    const float4* m4p = reinterpret_cast<const float4*>(mask) + ((row << 10) >> 2);
    const float4* a4p = reinterpret_cast<const float4*>(u) + (base0 >> 2);
    const float4* c4p = reinterpret_cast<const float4*>(u) + (base1 >> 2);

    // ---- 3 vector loads up front (MLP=3); mask is pure-streaming -> evict-first ----
    const float4 m4 = __ldcs(m4p + tid);
    const float4 a4 = a4p[tid];
    const float4 c4 = c4p[tid];

    const int b0 = (m4.x != 0.0f), b1 = (m4.y != 0.0f),
              b2 = (m4.z != 0.0f), b3 = (m4.w != 0.0f);
    const int mbits = b0 | (b1 << 1) | (b2 << 2) | (b3 << 3);

    const unsigned full = 0xffffffffu;

    // ---- per-warp first/second/last set positions ----
    const unsigned nz  = __ballot_sync(full, mbits != 0);
    const unsigned nz2 = nz & (nz - 1);
    const int t1 = nz  ? (__ffs(nz)  - 1) : 0;
    const int t2 = nz2 ? (__ffs(nz2) - 1) : 0;
    const int tL = nz  ? (31 - __clz(nz)) : 0;
    const int mt1 = __shfl_sync(full, mbits, t1);
    const int mt2 = __shfl_sync(full, mbits, t2);
    const int mtL = __shfl_sync(full, mbits, tL);

    const int wbase = wid << 7;
    int wf = BIG, ws = BIG, wl = -1;
    if (nz) {
        wf = wbase + (t1 << 2) + (__ffs(mt1) - 1);
        const int m1b = mt1 & (mt1 - 1);
        if (m1b)      ws = wbase + (t1 << 2) + (__ffs(m1b) - 1);
        else if (nz2) ws = wbase + (t2 << 2) + (__ffs(mt2) - 1);
        wl = wbase + (tL << 2) + (31 - __clz(mtL));
    }

    // ---- in-warp halo exchange ----
    int   ml = __shfl_up_sync  (full, b3,   1);
    float al = __shfl_up_sync  (full, a4.w, 1);
    float cl = __shfl_up_sync  (full, c4.w, 1);
    int   mr = __shfl_down_sync(full, b0,   1);
    float ar = __shfl_down_sync(full, a4.x, 1);
    float cr = __shfl_down_sync(full, c4.x, 1);

    if (lane == 31) {
        wfs[wid] = wf; wss[wid] = ws; wls[wid] = wl;
        em_last[wid] = b3; ea_last[wid] = a4.w; ec_last[wid] = c4.w;
    }
    if (lane == 0) {
        em_first[wid] = b0; ea_first[wid] = a4.x; ec_first[wid] = c4.x;
    }
    __syncthreads();

    // ---- O(1) warp-parallel merge of the 8 per-warp index triples ----
    const int idx8 = lane & 7;
    const int a8 = wfs[idx8];                // broadcast LDS
    const int s8 = wss[idx8];
    const int l8 = wls[idx8];
    const unsigned has = __ballot_sync(full, (lane < 8) && (a8 != BIG));

    int f1 = BIG, f2 = BIG, lastp = -1;
    if (has) {                               // warp-uniform branch
        const int w1 = __ffs(has) - 1;
        f1 = __shfl_sync(full, a8, w1);
        const int s1 = __shfl_sync(full, s8, w1);
        const unsigned has2 = has & (has - 1);
        const int w2 = has2 ? (__ffs(has2) - 1) : 0;
        const int a2 = __shfl_sync(full, a8, w2);
        f2 = (s1 != BIG) ? s1 : (has2 ? a2 : BIG);
        const int wlw = 31 - __clz(has);
        lastp = __shfl_sync(full, l8, wlw);
    }

    // ---- fix halos at warp boundaries (zero padding at row ends) ----
    if (lane == 0) {
        if (wid > 0) { ml = em_last[wid-1]; al = ea_last[wid-1]; cl = ec_last[wid-1]; }
        else         { ml = 0; al = 0.0f; cl = 0.0f; }
    }
    if (lane == 31) {
        if (wid < 7) { mr = em_first[wid+1]; ar = ea_first[wid+1]; cr = ec_first[wid+1]; }
        else         { mr = 0; ar = 0.0f; cr = 0.0f; }
    }

    // ---- per-element weights (shared across channels) ----
    const int i0 = tid << 2;
    const unsigned du = (unsigned)(f2 - f1);
    const int j  = i0 - f1;                  // e1: (unsigned)(j+k) < du
    const int jl = lastp - i0;               // e2: k == jl

    // erosion via 6-bit window: bit k of win = mask[i0-1+k]; er_k needs bits k..k+2
    const unsigned win = (unsigned)(ml != 0) | ((unsigned)mbits << 1)
                       | ((unsigned)(mr != 0) << 5);

    float wp[4], w0[4], wm[4];
    #pragma unroll
    for (int k = 0; k < 4; k++) {
        const float fer = (((win >> k) & 7u) == 7u) ? INV_2H : 0.0f;
        const float fe1 = ((unsigned)(j + k) < du)  ? INV_H  : 0.0f;
        const float fe2 = (k == jl)                 ? INV_H  : 0.0f;
        wp[k] = fer + fe1;
        w0[k] = fe2 - fe1;
        wm[k] = -(fer + fe2);
    }

    // ---- channel 0: 3 FMAs per element ----
    float4 rA;
    rA.x = fmaf(wp[0], a4.y, fmaf(w0[0], a4.x, wm[0] * al));
    rA.y = fmaf(wp[1], a4.z, fmaf(w0[1], a4.y, wm[1] * a4.x));
    rA.z = fmaf(wp[2], a4.w, fmaf(w0[2], a4.z, wm[2] * a4.y));
    rA.w = fmaf(wp[3], ar,   fmaf(w0[3], a4.w, wm[3] * a4.z));
    __stcs(reinterpret_cast<float4*>(out) + (base0 >> 2) + tid, rA);

    // ---- channel 1 ----
    float4 rC;
    rC.x = fmaf(wp[0], c4.y, fmaf(w0[0], c4.x, wm[0] * cl));
    rC.y = fmaf(wp[1], c4.z, fmaf(w0[1], c4.y, wm[1] * c4.x));
    rC.z = fmaf(wp[2], c4.w, fmaf(w0[2], c4.z, wm[2] * c4.y));
    rC.w = fmaf(wp[3], cr,   fmaf(w0[3], c4.w, wm[3] * c4.z));
    __stcs(reinterpret_cast<float4*>(out) + (base1 >> 2) + tid, rC);
}

extern "C" void kernel_launch(void* const* d_in, const int* in_sizes, int n_in,
                              void* d_out, int out_size)
{
    const float* u    = (const float*)d_in[0];
    const float* mask = (const float*)d_in[1];
    float* o = (float*)d_out;

    const int nrows = 16 * HEIGHT;   // one block per (b, y) row
    dnet_kernel<<<nrows, NT>>>(u, mask, o);
}